// round 11
// baseline (speedup 1.0000x reference)
#include <cuda_runtime.h>

// GlobalFilter: y = irfft2(rfft2(x, ortho) * W, ortho), 14x14 spatial, B=256, C=512.
// R11: R9 base (NC=32, 256 thr, 48 regs, 5 CTAs/SM) + k2=0/7 warp-specialized
//      stage B (real-symmetry: ~45% fewer ops on warps 0 and 7).
//      __ldcs/__stcs hints from R10 removed (correlated with ncu regression).

#define NC 32
#define NTHR 256

typedef unsigned long long u64;

__device__ __forceinline__ u64 pk2(float x, float y) {
    u64 r; asm("mov.b64 %0, {%1, %2};" : "=l"(r) : "f"(x), "f"(y)); return r;
}
__device__ __forceinline__ void upk2(u64 v, float& x, float& y) {
    asm("mov.b64 {%0, %1}, %2;" : "=f"(x), "=f"(y) : "l"(v));
}
__device__ __forceinline__ u64 f2fma(u64 a, u64 b, u64 c) {
    u64 d; asm("fma.rn.f32x2 %0, %1, %2, %3;" : "=l"(d) : "l"(a), "l"(b), "l"(c)); return d;
}
__device__ __forceinline__ u64 f2add(u64 a, u64 b) {
    u64 d; asm("add.rn.f32x2 %0, %1, %2;" : "=l"(d) : "l"(a), "l"(b)); return d;
}
__device__ __forceinline__ u64 f2sub(u64 a, u64 b) {
    u64 d; asm("sub.rn.f32x2 %0, %1, %2;" : "=l"(d) : "l"(a), "l"(b)); return d;
}
__device__ __forceinline__ u64 f2mul(u64 a, u64 b) {
    u64 d; asm("mul.rn.f32x2 %0, %1, %2;" : "=l"(d) : "l"(a), "l"(b)); return d;
}

__global__ __launch_bounds__(NTHR, 5) void gf_kernel(const float* __restrict__ x,
                                                     const float* __restrict__ w,
                                                     float* __restrict__ y) {
    __shared__ u64 E[14 * 8 * NC];   // interleaved complex (re, im) per channel, 28672 B

    const int b  = blockIdx.y;
    const int c0 = blockIdx.x * NC;
    const int tid = threadIdx.x;

    const float CC[14] = {
         1.0000000000000000f,  0.9009688679024191f,  0.6234898018587336f,
         0.2225209339563144f, -0.2225209339563143f, -0.6234898018587335f,
        -0.9009688679024191f, -1.0000000000000000f, -0.9009688679024191f,
        -0.6234898018587336f, -0.2225209339563146f,  0.2225209339563143f,
         0.6234898018587334f,  0.9009688679024190f
    };
    const float SS[14] = {
         0.0000000000000000f,  0.4338837391175581f,  0.7818314824680298f,
         0.9749279121818236f,  0.9749279121818236f,  0.7818314824680299f,
         0.4338837391175582f,  0.0000000000000000f, -0.4338837391175581f,
        -0.7818314824680297f, -0.9749279121818236f, -0.9749279121818238f,
        -0.7818314824680300f, -0.4338837391175583f
    };

    // ---- Stage A: rfft along q. 224 pair-tasks (2 channels each). ----
    if (tid < 224) {
        const int cp = (tid & 15) << 1;      // even channel within tile
        const int p  = tid >> 4;             // 0..13
        const float2* xp = reinterpret_cast<const float2*>(
            x + ((b * 196) + p * 14) * 512 + c0 + cp);

        u64 r[14];                           // lanes = (c0, c1)
        #pragma unroll
        for (int q = 0; q < 14; q++) {
            float2 t = xp[q * 256];
            r[q] = pk2(t.x, t.y);
        }
        u64 s[7], dd[7];
        #pragma unroll
        for (int j = 1; j <= 6; j++) {
            s[j]  = f2add(r[j], r[14 - j]);
            dd[j] = f2sub(r[j], r[14 - j]);
        }
        const u64 bs = f2add(r[0], r[7]);
        const u64 bd = f2sub(r[0], r[7]);
        {
            u64 e0 = bs, e7 = bd;
            #pragma unroll
            for (int j = 1; j <= 6; j++) {
                e0 = f2add(e0, s[j]);
                e7 = (j & 1) ? f2sub(e7, s[j]) : f2add(e7, s[j]);
            }
            float a0, a1, b0, b1;
            upk2(e0, a0, a1); upk2(e7, b0, b1);
            reinterpret_cast<float4*>(E + (p * 8 + 0) * NC + cp)[0] =
                make_float4(a0, 0.0f, a1, 0.0f);
            reinterpret_cast<float4*>(E + (p * 8 + 7) * NC + cp)[0] =
                make_float4(b0, 0.0f, b1, 0.0f);
        }
        #pragma unroll
        for (int k2 = 1; k2 <= 6; k2++) {
            u64 er = (k2 & 1) ? bd : bs;
            u64 ei = pk2(0.0f, 0.0f);
            #pragma unroll
            for (int j = 1; j <= 6; j++) {
                const int m = (k2 * j) % 14;
                er = f2fma(s[j],  pk2(CC[m], CC[m]), er);
                ei = f2fma(dd[j], pk2(-SS[m], -SS[m]), ei);
            }
            float er0, er1, ei0, ei1;
            upk2(er, er0, er1); upk2(ei, ei0, ei1);
            reinterpret_cast<float4*>(E + (p * 8 + k2) * NC + cp)[0] =
                make_float4(er0, ei0, er1, ei1);
        }
    }
    __syncthreads();

    // ---- Stage B: fft over p, * W/196, ifft over p. 1 task/thread. ----
    {
        const int c  = tid & (NC - 1);
        const int k2 = tid >> 5;
        u64* col = E + k2 * NC + c;
        const int PS = 8 * NC;               // 256
        const float inv196 = 1.0f / 196.0f;
        const float2* wp = reinterpret_cast<const float2*>(w) + k2 * 512 + c0 + c;

        if (k2 == 0 || k2 == 7) {
            // ---- special: real input (ei==0), only real output needed ----
            const float* colf = reinterpret_cast<const float*>(col);
            float r[14];
            #pragma unroll
            for (int p = 0; p < 14; p++) r[p] = colf[p * PS * 2];
            float sr[7], dr[7];
            #pragma unroll
            for (int j = 1; j <= 6; j++) {
                sr[j] = r[j] + r[14 - j];
                dr[j] = r[j] - r[14 - j];
            }
            const float bsr = r[0] + r[7], bdr = r[0] - r[7];
            float z0r = bsr, z7r = bdr;
            #pragma unroll
            for (int j = 1; j <= 6; j++) {
                z0r += sr[j];
                z7r += (j & 1) ? -sr[j] : sr[j];
            }
            const float2 wv0 = wp[0];
            const float2 wv7 = wp[7 * 8 * 512];
            const float Z0r = z0r * (wv0.x * inv196);   // imag of weighted DC/Nyq never needed
            const float Z7r = z7r * (wv7.x * inv196);

            float s2r[7], d2i[7];
            #pragma unroll
            for (int k1 = 1; k1 <= 6; k1++) {
                const float2 wvA = wp[k1 * 8 * 512];
                const float2 wvB = wp[(14 - k1) * 8 * 512];
                u64 AD = f2mul(pk2(sr[1], dr[1]), pk2(CC[k1 % 14], SS[k1 % 14]));
                #pragma unroll
                for (int j = 2; j <= 6; j++) {
                    const int m = (k1 * j) % 14;
                    AD = f2fma(pk2(sr[j], dr[j]), pk2(CC[m], SS[m]), AD);
                }
                float A, D; upk2(AD, A, D);
                const float xv = ((k1 & 1) ? bdr : bsr) + A;
                const float wAr = wvA.x * inv196, wAi = wvA.y * inv196;
                const float wBr = wvB.x * inv196, wBi = wvB.y * inv196;
                // Z[k1] = (xv, -D), Z[14-k1] = (xv, +D)
                const float zAr = xv * wAr + D * wAi, zAi = xv * wAi - D * wAr;
                const float zBr = xv * wBr - D * wBi, zBi = xv * wBi + D * wBr;
                s2r[k1] = zAr + zBr;
                d2i[k1] = zAi - zBi;
            }
            // inverse, real parts only
            const float bpr = Z0r + Z7r, bmr = Z0r - Z7r;
            float o0 = bpr, o7 = bmr;
            #pragma unroll
            for (int j = 1; j <= 6; j++) {
                o0 += s2r[j];
                o7 += (j & 1) ? -s2r[j] : s2r[j];
            }
            col[0]      = pk2(o0, 0.0f);
            col[7 * PS] = pk2(o7, 0.0f);
            #pragma unroll
            for (int p = 1; p <= 6; p++) {
                u64 AB = f2mul(pk2(s2r[1], d2i[1]), pk2(CC[p % 14], SS[p % 14]));
                #pragma unroll
                for (int j = 2; j <= 6; j++) {
                    const int m = (p * j) % 14;
                    AB = f2fma(pk2(s2r[j], d2i[j]), pk2(CC[m], SS[m]), AB);
                }
                float A, Bv; upk2(AB, A, Bv);
                const float base = (p & 1) ? bmr : bpr;
                col[p * PS]        = pk2(base + A - Bv, 0.0f);
                col[(14 - p) * PS] = pk2(base + A + Bv, 0.0f);
            }
        } else {
            // ---- general complex path (k2 = 1..6), as R9 ----
            const u64 e0 = col[0];
            const u64 e7 = col[7 * PS];
            u64 s[7], d[7];
            #pragma unroll
            for (int j = 1; j <= 6; j++) {
                u64 a = col[j * PS], bb = col[(14 - j) * PS];
                s[j] = f2add(a, bb);
                d[j] = f2sub(a, bb);
            }

            u64 z0, z7;
            {
                const float2 wv0 = wp[0];
                const float2 wv7 = wp[7 * 8 * 512];
                u64 a0 = f2add(e0, e7), a7 = f2sub(e0, e7);
                #pragma unroll
                for (int j = 1; j <= 6; j++) {
                    a0 = f2add(a0, s[j]);
                    a7 = (j & 1) ? f2sub(a7, s[j]) : f2add(a7, s[j]);
                }
                float zr, zi;
                upk2(a0, zr, zi);
                { const float wr = wv0.x * inv196, wi = wv0.y * inv196;
                  z0 = pk2(zr * wr - zi * wi, zr * wi + zi * wr); }
                upk2(a7, zr, zi);
                { const float wr = wv7.x * inv196, wi = wv7.y * inv196;
                  z7 = pk2(zr * wr - zi * wi, zr * wi + zi * wr); }
            }

            const u64 bp = f2add(e0, e7);
            const u64 bm = f2sub(e0, e7);
            u64 s2[7], d2[7];
            #pragma unroll
            for (int k1 = 1; k1 <= 6; k1++) {
                const float2 wvA = wp[k1 * 8 * 512];
                const float2 wvB = wp[(14 - k1) * 8 * 512];
                u64 AC = f2mul(s[1], pk2(CC[k1 % 14], CC[k1 % 14]));
                u64 DB = f2mul(d[1], pk2(SS[k1 % 14], SS[k1 % 14]));
                #pragma unroll
                for (int j = 2; j <= 6; j++) {
                    const int m = (k1 * j) % 14;
                    AC = f2fma(s[j], pk2(CC[m], CC[m]), AC);
                    DB = f2fma(d[j], pk2(SS[m], SS[m]), DB);
                }
                float A, C, D, Bv, bR, bI;
                upk2(AC, A, C); upk2(DB, D, Bv);
                upk2((k1 & 1) ? bm : bp, bR, bI);
                const float zra = bR + A + Bv, zia = bI + C - D;
                const float zrb = bR + A - Bv, zib = bI + C + D;
                float wAr = wvA.x * inv196, wAi = wvA.y * inv196;
                float wBr = wvB.x * inv196, wBi = wvB.y * inv196;
                const float zAr = zra * wAr - zia * wAi, zAi = zra * wAi + zia * wAr;
                const float zBr = zrb * wBr - zib * wBi, zBi = zrb * wBi + zib * wBr;
                s2[k1] = pk2(zAr + zBr, zAi + zBi);
                d2[k1] = pk2(zAr - zBr, zAi - zBi);
            }

            const u64 zp = f2add(z0, z7);
            const u64 zm = f2sub(z0, z7);
            {
                u64 o0 = zp, o7 = zm;
                #pragma unroll
                for (int j = 1; j <= 6; j++) {
                    o0 = f2add(o0, s2[j]);
                    o7 = (j & 1) ? f2sub(o7, s2[j]) : f2add(o7, s2[j]);
                }
                col[0]      = o0;
                col[7 * PS] = o7;
            }
            #pragma unroll
            for (int p = 1; p <= 6; p++) {
                u64 AC = f2mul(s2[1], pk2(CC[p % 14], CC[p % 14]));
                u64 DB = f2mul(d2[1], pk2(SS[p % 14], SS[p % 14]));
                #pragma unroll
                for (int j = 2; j <= 6; j++) {
                    const int m = (p * j) % 14;
                    AC = f2fma(s2[j], pk2(CC[m], CC[m]), AC);
                    DB = f2fma(d2[j], pk2(SS[m], SS[m]), DB);
                }
                float A, C, D, Bv, bR, bI;
                upk2(AC, A, C); upk2(DB, D, Bv);
                upk2((p & 1) ? zm : zp, bR, bI);
                col[p * PS]        = pk2(bR + A - Bv, bI + C + D);
                col[(14 - p) * PS] = pk2(bR + A + Bv, bI + C - D);
            }
        }
    }
    __syncthreads();

    // ---- Stage A': irfft along q. 224 pair-tasks (2 channels each). ----
    if (tid < 224) {
        const int cp = (tid & 15) << 1;
        const int p  = tid >> 4;
        const float4* row = reinterpret_cast<const float4*>(E + (p * 8) * NC + cp);

        u64 ea[8], eb[8];
        u64 rr[8];
        #pragma unroll
        for (int k2 = 0; k2 < 8; k2++) {
            float4 t = row[k2 * (NC / 2)];
            ea[k2] = pk2(t.x, t.y);
            eb[k2] = pk2(t.z, t.w);
            rr[k2] = pk2(t.x, t.z);
        }

        float2* yout = reinterpret_cast<float2*>(
            y + ((b * 196) + p * 14) * 512 + c0 + cp);

        const u64 base_e = f2add(rr[0], rr[7]);
        const u64 base_o = f2sub(rr[0], rr[7]);
        {
            u64 v0 = base_e, v7 = base_o;
            const u64 two_ = pk2(2.0f, 2.0f);
            const u64 ntwo = pk2(-2.0f, -2.0f);
            #pragma unroll
            for (int k2 = 1; k2 <= 6; k2++) {
                v0 = f2fma(rr[k2], two_, v0);
                v7 = f2fma(rr[k2], (k2 & 1) ? ntwo : two_, v7);
            }
            float v00, v01, v70, v71;
            upk2(v0, v00, v01); upk2(v7, v70, v71);
            yout[0]       = make_float2(v00, v01);
            yout[7 * 256] = make_float2(v70, v71);
        }
        #pragma unroll
        for (int q = 1; q <= 6; q++) {
            u64 AB0 = f2mul(ea[1], pk2(2.0f * CC[q % 14], 2.0f * SS[q % 14]));
            u64 AB1 = f2mul(eb[1], pk2(2.0f * CC[q % 14], 2.0f * SS[q % 14]));
            #pragma unroll
            for (int k2 = 2; k2 <= 6; k2++) {
                const int m = (k2 * q) % 14;
                const u64 tw = pk2(2.0f * CC[m], 2.0f * SS[m]);
                AB0 = f2fma(ea[k2], tw, AB0);
                AB1 = f2fma(eb[k2], tw, AB1);
            }
            float A0, B0, A1, B1, bc0, bc1;
            upk2(AB0, A0, B0); upk2(AB1, A1, B1);
            upk2((q & 1) ? base_o : base_e, bc0, bc1);
            yout[q * 256]        = make_float2(bc0 + A0 - B0, bc1 + A1 - B1);
            yout[(14 - q) * 256] = make_float2(bc0 + A0 + B0, bc1 + A1 + B1);
        }
    }
}

extern "C" void kernel_launch(void* const* d_in, const int* in_sizes, int n_in,
                              void* d_out, int out_size) {
    const float* x = (const float*)d_in[0];        // [256,196,512] f32
    const float* w = (const float*)d_in[1];        // [14,8,512,2]  f32
    float* y = (float*)d_out;                      // [256,196,512] f32

    dim3 grid(512 / NC, 256);                      // 16 x 256 = 4096 CTAs
    gf_kernel<<<grid, NTHR>>>(x, w, y);
}

// round 12
// speedup vs baseline: 1.0448x; 1.0448x over previous
#include <cuda_runtime.h>

// GlobalFilter: y = irfft2(rfft2(x, ortho) * W, ortho), 14x14 spatial, B=256, C=512.
// R12 (final): revert to R6 — the measured optimum across R6..R11 probes.
//   - Stages A/A': 2 adjacent channels per thread (channel-lane f32x2),
//     LDG.64/STG.64 global + LDS.128/STS.128 shared, single-task (224 tasks).
//   - Stage B: per-(k2,c) complex-lane f32x2, folded + output-paired 14-pt
//     DFTs, weight multiply fused into the k1 pair loop.
//   - NC=32, 256 threads, 28KB smem, 4 CTAs/SM.

#define NC 32
#define NTHR 256

typedef unsigned long long u64;

__device__ __forceinline__ u64 pk2(float x, float y) {
    u64 r; asm("mov.b64 %0, {%1, %2};" : "=l"(r) : "f"(x), "f"(y)); return r;
}
__device__ __forceinline__ void upk2(u64 v, float& x, float& y) {
    asm("mov.b64 {%0, %1}, %2;" : "=f"(x), "=f"(y) : "l"(v));
}
__device__ __forceinline__ u64 f2fma(u64 a, u64 b, u64 c) {
    u64 d; asm("fma.rn.f32x2 %0, %1, %2, %3;" : "=l"(d) : "l"(a), "l"(b), "l"(c)); return d;
}
__device__ __forceinline__ u64 f2add(u64 a, u64 b) {
    u64 d; asm("add.rn.f32x2 %0, %1, %2;" : "=l"(d) : "l"(a), "l"(b)); return d;
}
__device__ __forceinline__ u64 f2sub(u64 a, u64 b) {
    u64 d; asm("sub.rn.f32x2 %0, %1, %2;" : "=l"(d) : "l"(a), "l"(b)); return d;
}
__device__ __forceinline__ u64 f2mul(u64 a, u64 b) {
    u64 d; asm("mul.rn.f32x2 %0, %1, %2;" : "=l"(d) : "l"(a), "l"(b)); return d;
}

__global__ __launch_bounds__(NTHR, 4) void gf_kernel(const float* __restrict__ x,
                                                     const float* __restrict__ w,
                                                     float* __restrict__ y) {
    __shared__ u64 E[14 * 8 * NC];   // interleaved complex (re, im) per channel, 28672 B

    const int b  = blockIdx.y;
    const int c0 = blockIdx.x * NC;
    const int tid = threadIdx.x;

    const float CC[14] = {
         1.0000000000000000f,  0.9009688679024191f,  0.6234898018587336f,
         0.2225209339563144f, -0.2225209339563143f, -0.6234898018587335f,
        -0.9009688679024191f, -1.0000000000000000f, -0.9009688679024191f,
        -0.6234898018587336f, -0.2225209339563146f,  0.2225209339563143f,
         0.6234898018587334f,  0.9009688679024190f
    };
    const float SS[14] = {
         0.0000000000000000f,  0.4338837391175581f,  0.7818314824680298f,
         0.9749279121818236f,  0.9749279121818236f,  0.7818314824680299f,
         0.4338837391175582f,  0.0000000000000000f, -0.4338837391175581f,
        -0.7818314824680297f, -0.9749279121818236f, -0.9749279121818238f,
        -0.7818314824680300f, -0.4338837391175583f
    };

    // ---- Stage A: rfft along q. 224 pair-tasks (2 channels each). ----
    if (tid < 224) {
        const int cp = (tid & 15) << 1;      // even channel within tile
        const int p  = tid >> 4;             // 0..13
        const float2* xp = reinterpret_cast<const float2*>(
            x + ((b * 196) + p * 14) * 512 + c0 + cp);

        u64 r[14];                           // lanes = (c0, c1)
        #pragma unroll
        for (int q = 0; q < 14; q++) {
            float2 t = xp[q * 256];
            r[q] = pk2(t.x, t.y);
        }
        u64 s[7], dd[7];
        #pragma unroll
        for (int j = 1; j <= 6; j++) {
            s[j]  = f2add(r[j], r[14 - j]);
            dd[j] = f2sub(r[j], r[14 - j]);
        }
        const u64 bs = f2add(r[0], r[7]);
        const u64 bd = f2sub(r[0], r[7]);
        {
            u64 e0 = bs, e7 = bd;
            #pragma unroll
            for (int j = 1; j <= 6; j++) {
                e0 = f2add(e0, s[j]);
                e7 = (j & 1) ? f2sub(e7, s[j]) : f2add(e7, s[j]);
            }
            float a0, a1, b0, b1;
            upk2(e0, a0, a1); upk2(e7, b0, b1);
            reinterpret_cast<float4*>(E + (p * 8 + 0) * NC + cp)[0] =
                make_float4(a0, 0.0f, a1, 0.0f);
            reinterpret_cast<float4*>(E + (p * 8 + 7) * NC + cp)[0] =
                make_float4(b0, 0.0f, b1, 0.0f);
        }
        #pragma unroll
        for (int k2 = 1; k2 <= 6; k2++) {
            u64 er = (k2 & 1) ? bd : bs;
            u64 ei = pk2(0.0f, 0.0f);
            #pragma unroll
            for (int j = 1; j <= 6; j++) {
                const int m = (k2 * j) % 14;
                er = f2fma(s[j],  pk2(CC[m], CC[m]), er);
                ei = f2fma(dd[j], pk2(-SS[m], -SS[m]), ei);
            }
            float er0, er1, ei0, ei1;
            upk2(er, er0, er1); upk2(ei, ei0, ei1);
            reinterpret_cast<float4*>(E + (p * 8 + k2) * NC + cp)[0] =
                make_float4(er0, ei0, er1, ei1);
        }
    }
    __syncthreads();

    // ---- Stage B: fft over p, * W/196 (fused), ifft over p. 1 task/thread. ----
    {
        const int c  = tid & (NC - 1);
        const int k2 = tid >> 5;
        u64* col = E + k2 * NC + c;          // element (p) at col[p * 8*NC]
        const int PS = 8 * NC;               // 256

        const u64 e0 = col[0];
        const u64 e7 = col[7 * PS];
        u64 s[7], d[7];
        #pragma unroll
        for (int j = 1; j <= 6; j++) {
            u64 a = col[j * PS], bb = col[(14 - j) * PS];
            s[j] = f2add(a, bb);
            d[j] = f2sub(a, bb);
        }

        const float inv196 = 1.0f / 196.0f;
        const float2* wp = reinterpret_cast<const float2*>(w) + k2 * 512 + c0 + c;

        u64 z[14];
        const u64 bp = f2add(e0, e7);
        const u64 bm = f2sub(e0, e7);
        {
            const float2 wv0 = wp[0];
            const float2 wv7 = wp[7 * 8 * 512];
            u64 z0 = bp, z7 = bm;
            #pragma unroll
            for (int j = 1; j <= 6; j++) {
                z0 = f2add(z0, s[j]);
                z7 = (j & 1) ? f2sub(z7, s[j]) : f2add(z7, s[j]);
            }
            float zr, zi;
            upk2(z0, zr, zi);
            { const float wr = wv0.x * inv196, wi = wv0.y * inv196;
              z[0] = pk2(zr * wr - zi * wi, zr * wi + zi * wr); }
            upk2(z7, zr, zi);
            { const float wr = wv7.x * inv196, wi = wv7.y * inv196;
              z[7] = pk2(zr * wr - zi * wi, zr * wi + zi * wr); }
        }
        #pragma unroll
        for (int k1 = 1; k1 <= 6; k1++) {
            const float2 wvA = wp[k1 * 8 * 512];
            const float2 wvB = wp[(14 - k1) * 8 * 512];
            u64 AC = f2mul(s[1], pk2(CC[k1 % 14], CC[k1 % 14]));
            u64 DB = f2mul(d[1], pk2(SS[k1 % 14], SS[k1 % 14]));
            #pragma unroll
            for (int j = 2; j <= 6; j++) {
                const int m = (k1 * j) % 14;
                AC = f2fma(s[j], pk2(CC[m], CC[m]), AC);
                DB = f2fma(d[j], pk2(SS[m], SS[m]), DB);
            }
            float A, C, D, Bv, bR, bI;
            upk2(AC, A, C); upk2(DB, D, Bv);
            upk2((k1 & 1) ? bm : bp, bR, bI);
            const float zra = bR + A + Bv, zia = bI + C - D;
            const float zrb = bR + A - Bv, zib = bI + C + D;
            { const float wr = wvA.x * inv196, wi = wvA.y * inv196;
              z[k1] = pk2(zra * wr - zia * wi, zra * wi + zia * wr); }
            { const float wr = wvB.x * inv196, wi = wvB.y * inv196;
              z[14 - k1] = pk2(zrb * wr - zib * wi, zrb * wi + zib * wr); }
        }

        const u64 zp = f2add(z[0], z[7]);
        const u64 zm = f2sub(z[0], z[7]);
        u64 s2[7], d2[7];
        #pragma unroll
        for (int j = 1; j <= 6; j++) {
            s2[j] = f2add(z[j], z[14 - j]);
            d2[j] = f2sub(z[j], z[14 - j]);
        }
        {
            u64 o0 = zp, o7 = zm;
            #pragma unroll
            for (int j = 1; j <= 6; j++) {
                o0 = f2add(o0, s2[j]);
                o7 = (j & 1) ? f2sub(o7, s2[j]) : f2add(o7, s2[j]);
            }
            col[0]      = o0;
            col[7 * PS] = o7;
        }
        #pragma unroll
        for (int p = 1; p <= 6; p++) {
            u64 AC = f2mul(s2[1], pk2(CC[p % 14], CC[p % 14]));
            u64 DB = f2mul(d2[1], pk2(SS[p % 14], SS[p % 14]));
            #pragma unroll
            for (int j = 2; j <= 6; j++) {
                const int m = (p * j) % 14;
                AC = f2fma(s2[j], pk2(CC[m], CC[m]), AC);
                DB = f2fma(d2[j], pk2(SS[m], SS[m]), DB);
            }
            float A, C, D, Bv, bR, bI;
            upk2(AC, A, C); upk2(DB, D, Bv);
            upk2((p & 1) ? zm : zp, bR, bI);
            col[p * PS]        = pk2(bR + A - Bv, bI + C + D);
            col[(14 - p) * PS] = pk2(bR + A + Bv, bI + C - D);
        }
    }
    __syncthreads();

    // ---- Stage A': irfft along q. 224 pair-tasks (2 channels each). ----
    if (tid < 224) {
        const int cp = (tid & 15) << 1;
        const int p  = tid >> 4;
        const float4* row = reinterpret_cast<const float4*>(E + (p * 8) * NC + cp);

        u64 ea[8], eb[8];
        u64 rr[8];
        #pragma unroll
        for (int k2 = 0; k2 < 8; k2++) {
            float4 t = row[k2 * (NC / 2)];
            ea[k2] = pk2(t.x, t.y);
            eb[k2] = pk2(t.z, t.w);
            rr[k2] = pk2(t.x, t.z);
        }

        float2* yout = reinterpret_cast<float2*>(
            y + ((b * 196) + p * 14) * 512 + c0 + cp);

        const u64 base_e = f2add(rr[0], rr[7]);
        const u64 base_o = f2sub(rr[0], rr[7]);
        {
            u64 v0 = base_e, v7 = base_o;
            const u64 two_ = pk2(2.0f, 2.0f);
            const u64 ntwo = pk2(-2.0f, -2.0f);
            #pragma unroll
            for (int k2 = 1; k2 <= 6; k2++) {
                v0 = f2fma(rr[k2], two_, v0);
                v7 = f2fma(rr[k2], (k2 & 1) ? ntwo : two_, v7);
            }
            float v00, v01, v70, v71;
            upk2(v0, v00, v01); upk2(v7, v70, v71);
            yout[0]       = make_float2(v00, v01);
            yout[7 * 256] = make_float2(v70, v71);
        }
        #pragma unroll
        for (int q = 1; q <= 6; q++) {
            u64 AB0 = f2mul(ea[1], pk2(2.0f * CC[q % 14], 2.0f * SS[q % 14]));
            u64 AB1 = f2mul(eb[1], pk2(2.0f * CC[q % 14], 2.0f * SS[q % 14]));
            #pragma unroll
            for (int k2 = 2; k2 <= 6; k2++) {
                const int m = (k2 * q) % 14;
                const u64 tw = pk2(2.0f * CC[m], 2.0f * SS[m]);
                AB0 = f2fma(ea[k2], tw, AB0);
                AB1 = f2fma(eb[k2], tw, AB1);
            }
            float A0, B0, A1, B1, bc0, bc1;
            upk2(AB0, A0, B0); upk2(AB1, A1, B1);
            upk2((q & 1) ? base_o : base_e, bc0, bc1);
            yout[q * 256]        = make_float2(bc0 + A0 - B0, bc1 + A1 - B1);
            yout[(14 - q) * 256] = make_float2(bc0 + A0 + B0, bc1 + A1 + B1);
        }
    }
}

extern "C" void kernel_launch(void* const* d_in, const int* in_sizes, int n_in,
                              void* d_out, int out_size) {
    const float* x = (const float*)d_in[0];        // [256,196,512] f32
    const float* w = (const float*)d_in[1];        // [14,8,512,2]  f32
    float* y = (float*)d_out;                      // [256,196,512] f32

    dim3 grid(512 / NC, 256);                      // 16 x 256 = 4096 CTAs
    gf_kernel<<<grid, NTHR>>>(x, w, y);
}